// round 5
// baseline (speedup 1.0000x reference)
#include <cuda_runtime.h>
#include <math.h>

#define NN 50000
#define NE 800000
#define NG 1024
#define IND 25
#define DIM 64
#define STEPS 3

// ---------------- device scratch (statically allocated; no cudaMalloc) ------
__device__ float g_hw[NN * DIM];      // relu(x@W0+b0) @ Wc
__device__ float g_h2[NN * DIM];      // relu(agg + bc)  -> set2set input
__device__ float g_dinv[NN];
__device__ int   g_deg[NN];           // degree incl. self loop
__device__ int   g_cur[NN];           // placement cursors
__device__ int   g_coff[NN + 1];      // CSR offsets (in-edges, excl. self)
__device__ int   g_src[NE];           // CSR source list
__device__ int   g_goff[NG + 1];      // per-graph node ranges (batch sorted)
__device__ float g_hs[NG * DIM];
__device__ float g_cs[NG * DIM];
__device__ float g_qstar[NG * 2 * DIM];
__device__ float g_gates[NG * 4 * DIM];

// ---------------- init: zero states/cursors, deg=1 (self loop) --------------
__global__ void k_init() {
    int t = blockIdx.x * 256 + threadIdx.x;          // 131072 threads
    if (t < NG * DIM)     { g_hs[t] = 0.f; g_cs[t] = 0.f; }
    if (t < NG * 2 * DIM) g_qstar[t] = 0.f;
    if (t < NN)           { g_deg[t] = 1; g_cur[t] = 0; }
}

// ---------------- fused lin0(+relu) and @Wc, 8 nodes per iter ---------------
__global__ void k_lin0(const float* __restrict__ x, const float* __restrict__ W0,
                       const float* __restrict__ b0, const float* __restrict__ Wc) {
    __shared__ float sW0[IND * DIM];
    __shared__ float sWc[DIM * DIM];
    __shared__ float sb0[DIM];
    __shared__ float sx[8][IND + 1];
    __shared__ float sh[8][DIM];
    int tid = threadIdx.x;                           // 256 threads
    for (int i = tid; i < IND * DIM; i += 256) sW0[i] = W0[i];
    for (int i = tid; i < DIM * DIM; i += 256) sWc[i] = Wc[i];
    if (tid < DIM) sb0[tid] = b0[tid];
    __syncthreads();
    int d = tid & 63, l0 = tid >> 6;                 // l0 in 0..3
    for (int base = blockIdx.x * 8; base < NN; base += gridDim.x * 8) {
        for (int i = tid; i < 8 * IND; i += 256) {
            int nn = i / IND, kk = i % IND;
            int node = base + nn;
            sx[nn][kk] = (node < NN) ? x[node * IND + kk] : 0.f;
        }
        __syncthreads();
        #pragma unroll
        for (int ln = l0; ln < 8; ln += 4) {
            float acc = sb0[d];
            #pragma unroll
            for (int k = 0; k < IND; k++) acc += sx[ln][k] * sW0[k * DIM + d];
            sh[ln][d] = fmaxf(acc, 0.f);
        }
        __syncthreads();
        #pragma unroll
        for (int ln = l0; ln < 8; ln += 4) {
            float acc2 = 0.f;
            #pragma unroll
            for (int k = 0; k < DIM; k++) acc2 += sh[ln][k] * sWc[k * DIM + d];
            int node = base + ln;
            if (node < NN) g_hw[node * DIM + d] = acc2;
        }
        __syncthreads();
    }
}

// ------ degree histogram + graph-range boundaries (batch is SORTED) ---------
__global__ void k_pre(const int* __restrict__ ei, const int* __restrict__ batch) {
    int t = blockIdx.x * 256 + threadIdx.x;
    if (t < NE) atomicAdd(&g_deg[ei[NE + t]], 1);
    if (t < NN) {
        int bt = batch[t];
        if (t == 0) {
            for (int g = 0; g <= bt; g++) g_goff[g] = 0;
        } else {
            int bp = batch[t - 1];
            for (int g = bp + 1; g <= bt; g++) g_goff[g] = t;
        }
        if (t == NN - 1) {
            for (int g = bt + 1; g <= NG; g++) g_goff[g] = NN;
        }
    }
}

// ------ single-block scan: coff = exclusive-scan(deg-1), plus dinv ----------
__global__ void k_scan() {
    __shared__ int s[1024];
    const int C = (NN + 1023) / 1024;                // 49
    int t = threadIdx.x;
    int b = t * C, e = min(b + C, NN);
    int sum = 0;
    for (int i = b; i < e; i++) sum += g_deg[i] - 1;
    s[t] = sum;
    __syncthreads();
    for (int off = 1; off < 1024; off <<= 1) {
        int v = (t >= off) ? s[t - off] : 0;
        __syncthreads();
        s[t] += v;
        __syncthreads();
    }
    int run = t ? s[t - 1] : 0;
    for (int i = b; i < e; i++) {
        int dg = g_deg[i];
        g_coff[i] = run;
        run += dg - 1;
        g_dinv[i] = rsqrtf((float)dg);
    }
    if (e == NN && b < NN) g_coff[NN] = run;
}

// ------ CSR placement: src list grouped by target ---------------------------
__global__ void k_place(const int* __restrict__ ei) {
    int t = blockIdx.x * 256 + threadIdx.x;
    if (t >= NE) return;
    int r = ei[t];
    int c = ei[NE + t];
    int pos = atomicAdd(&g_cur[c], 1);
    g_src[g_coff[c] + pos] = r;
}

// ------ gather (no atomics): h2 = relu(self + sum_in norm*hw[src] + bc) -----
// one warp per node; lane holds 2 dims (float2).
__global__ void k_gather(const float* __restrict__ bc) {
    int n = blockIdx.x * 8 + (threadIdx.x >> 5);
    if (n >= NN) return;
    int lane = threadIdx.x & 31;
    float dn = g_dinv[n];
    float2 hv = ((const float2*)g_hw)[n * 32 + lane];
    float s2 = dn * dn;
    float ax = s2 * hv.x, ay = s2 * hv.y;            // self-loop term
    int e0 = g_coff[n], e1 = g_coff[n + 1];
    for (int base = e0; base < e1; base += 32) {
        int m = min(32, e1 - base);
        int s = (lane < m) ? g_src[base + lane] : 0;
        for (int j = 0; j < m; j++) {
            int sj = __shfl_sync(0xffffffffu, s, j);
            float norm = g_dinv[sj] * dn;
            float2 v = ((const float2*)g_hw)[sj * 32 + lane];
            ax += norm * v.x;
            ay += norm * v.y;
        }
    }
    float2 b = ((const float2*)bc)[lane];
    float2 o;
    o.x = fmaxf(ax + b.x, 0.f);
    o.y = fmaxf(ay + b.y, 0.f);
    ((float2*)g_h2)[n * 32 + lane] = o;
}

// ---------------- LSTM gates: gates = qstar@Wih^T + hs@Whh^T + b -----------
__global__ void k_gates(const float* __restrict__ Wih, const float* __restrict__ Whh,
                        const float* __restrict__ bih, const float* __restrict__ bhh) {
    __shared__ float sq[32][129];
    __shared__ float shh[32][65];
    int g0 = blockIdx.x * 32;
    int j0 = blockIdx.y * 32;
    int tid = threadIdx.x;                           // 256
    for (int i = tid; i < 32 * 128; i += 256) {
        int g = i >> 7, k = i & 127;
        sq[g][k] = g_qstar[(g0 + g) * 128 + k];
    }
    for (int i = tid; i < 32 * 64; i += 256) {
        int g = i >> 6, k = i & 63;
        shh[g][k] = g_hs[(g0 + g) * 64 + k];
    }
    __syncthreads();
    int warp = tid >> 5, lane = tid & 31;            // lane = graph
    for (int jj = warp; jj < 32; jj += 8) {
        int j = j0 + jj;
        const float4* wi4 = (const float4*)(Wih + j * 128);
        const float2* wh2 = (const float2*)(Whh + j * 64);
        float acc = bih[j] + bhh[j];
        #pragma unroll
        for (int k4 = 0; k4 < 32; k4++) {
            float4 w = wi4[k4];
            acc += w.x * sq[lane][k4 * 4 + 0] + w.y * sq[lane][k4 * 4 + 1]
                 + w.z * sq[lane][k4 * 4 + 2] + w.w * sq[lane][k4 * 4 + 3];
        }
        #pragma unroll
        for (int k2 = 0; k2 < 32; k2++) {
            float2 w = wh2[k2];
            acc += w.x * shh[lane][k2 * 2 + 0] + w.y * shh[lane][k2 * 2 + 1];
        }
        g_gates[(g0 + lane) * 256 + j] = acc;
    }
}

// ------ fused LSTM cell + single-pass online-softmax attention --------------
// one block per graph, 128 threads (4 warps).
__global__ void k_attn() {
    int g = blockIdx.x;
    int tid = threadIdx.x;
    int warp = tid >> 5, lane = tid & 31;
    __shared__ float sqv[DIM];
    __shared__ float sm[4], ssm[4];
    __shared__ float sr[4][DIM];
    // LSTM cell for this graph (q = new h)
    if (tid < DIM) {
        const float* gt = g_gates + g * 256;
        float i = 1.f / (1.f + __expf(-gt[tid]));
        float f = 1.f / (1.f + __expf(-gt[64 + tid]));
        float gg = tanhf(gt[128 + tid]);
        float o = 1.f / (1.f + __expf(-gt[192 + tid]));
        float c = f * g_cs[g * DIM + tid] + i * gg;
        float h = o * tanhf(c);
        g_cs[g * DIM + tid] = c;
        g_hs[g * DIM + tid] = h;
        sqv[tid] = h;
    }
    __syncthreads();
    int start = g_goff[g], end = g_goff[g + 1];
    float q2x = sqv[lane * 2], q2y = sqv[lane * 2 + 1];
    // single pass: online softmax with warp-wide running max
    float m = -1e30f, wsum = 0.f, rx = 0.f, ry = 0.f;
    for (int v = start + warp; v < end; v += 4) {
        float2 hv = ((const float2*)g_h2)[v * 32 + lane];
        float d = hv.x * q2x + hv.y * q2y;
        d += __shfl_xor_sync(0xffffffffu, d, 16);
        d += __shfl_xor_sync(0xffffffffu, d, 8);
        d += __shfl_xor_sync(0xffffffffu, d, 4);
        d += __shfl_xor_sync(0xffffffffu, d, 2);
        d += __shfl_xor_sync(0xffffffffu, d, 1);
        float nm = fmaxf(m, d);
        float sc = __expf(m - nm);                   // 0 when m was -inf-ish
        float w = __expf(d - nm);
        wsum = wsum * sc + w;
        rx = rx * sc + w * hv.x;
        ry = ry * sc + w * hv.y;
        m = nm;
    }
    if (lane == 0) { sm[warp] = m; ssm[warp] = wsum; }
    sr[warp][lane * 2] = rx;
    sr[warp][lane * 2 + 1] = ry;
    __syncthreads();
    if (tid < DIM) {
        float M = fmaxf(fmaxf(sm[0], sm[1]), fmaxf(sm[2], sm[3]));
        float tot = 0.f, racc = 0.f;
        #pragma unroll
        for (int w = 0; w < 4; w++) {
            float e = __expf(sm[w] - M);
            tot += ssm[w] * e;
            racc += sr[w][tid] * e;
        }
        float r = (end > start) ? racc / tot : 0.f;  // empty graph -> r = 0
        g_qstar[g * 128 + tid] = sqv[tid];
        g_qstar[g * 128 + DIM + tid] = r;
    }
}

// ---------------- readout: relu(qstar@W1+b1)@W2 + b2 ------------------------
__global__ void k_readout(const float* __restrict__ W1, const float* __restrict__ b1,
                          const float* __restrict__ W2, const float* __restrict__ b2,
                          float* __restrict__ out) {
    int g = blockIdx.x;
    int d = threadIdx.x;                             // 64
    __shared__ float sq[128];
    __shared__ float red[64];
    sq[d] = g_qstar[g * 128 + d];
    sq[64 + d] = g_qstar[g * 128 + 64 + d];
    __syncthreads();
    float acc = b1[d];
    #pragma unroll
    for (int k = 0; k < 128; k++) acc += sq[k] * W1[k * 64 + d];
    acc = fmaxf(acc, 0.f) * W2[d];
    red[d] = acc;
    __syncthreads();
    for (int s = 32; s > 0; s >>= 1) {
        if (d < s) red[d] += red[d + s];
        __syncthreads();
    }
    if (d == 0) out[g] = red[0] + b2[0];
}

// ---------------- launch sequence -------------------------------------------
extern "C" void kernel_launch(void* const* d_in, const int* in_sizes, int n_in,
                              void* d_out, int out_size) {
    const float* x     = (const float*)d_in[0];
    const int*   ei    = (const int*)  d_in[1];
    const int*   batch = (const int*)  d_in[2];
    const float* W0    = (const float*)d_in[3];
    const float* b0    = (const float*)d_in[4];
    const float* Wc    = (const float*)d_in[5];
    const float* bc    = (const float*)d_in[6];
    const float* Wih   = (const float*)d_in[7];
    const float* Whh   = (const float*)d_in[8];
    const float* bih   = (const float*)d_in[9];
    const float* bhh   = (const float*)d_in[10];
    const float* W1    = (const float*)d_in[11];
    const float* b1    = (const float*)d_in[12];
    const float* W2    = (const float*)d_in[13];
    const float* b2    = (const float*)d_in[14];
    float* out = (float*)d_out;

    k_init<<<512, 256>>>();
    k_lin0<<<512, 256>>>(x, W0, b0, Wc);
    k_pre<<<(NE + 255) / 256, 256>>>(ei, batch);
    k_scan<<<1, 1024>>>();
    k_place<<<(NE + 255) / 256, 256>>>(ei);
    k_gather<<<(NN + 7) / 8, 256>>>(bc);
    for (int s = 0; s < STEPS; s++) {
        k_gates<<<dim3(32, 8), 256>>>(Wih, Whh, bih, bhh);
        k_attn<<<NG, 128>>>();
    }
    k_readout<<<NG, 64>>>(W1, b1, W2, b2, out);
}

// round 6
// speedup vs baseline: 1.3759x; 1.3759x over previous
#include <cuda_runtime.h>
#include <math.h>

#define NN 50000
#define NE 800000
#define NG 1024
#define IND 25
#define DIM 64
#define STEPS 3
#define SCAN_B 196                     // ceil(NN/256)

// ---------------- device scratch (statically allocated; no cudaMalloc) ------
__device__ float g_hw[NN * DIM];      // relu(x@W0+b0) @ Wc
__device__ float g_h2[NN * DIM];      // relu(agg + bc)  -> set2set input
__device__ float g_dinv[NN];
__device__ int   g_deg[NN];           // degree incl. self loop
__device__ int   g_cur[NN];           // placement cursors
__device__ int   g_coff[NN + 1];      // CSR offsets (in-edges, excl. self)
__device__ int   g_src[NE];           // CSR source list
__device__ int   g_goff[NG + 1];      // per-graph node ranges (batch sorted)
__device__ int   g_bsum[SCAN_B];      // per-block partial sums
__device__ int   g_boff[SCAN_B];      // scanned block offsets
__device__ float g_hs[NG * DIM];
__device__ float g_cs[NG * DIM];
__device__ float g_qstar[NG * 2 * DIM];
__device__ float g_gates[NG * 4 * DIM];

// ---------------- init: zero states/cursors, deg=1 (self loop) --------------
__global__ void k_init() {
    int t = blockIdx.x * 256 + threadIdx.x;          // 131072 threads
    if (t < NG * DIM)     { g_hs[t] = 0.f; g_cs[t] = 0.f; }
    if (t < NG * 2 * DIM) g_qstar[t] = 0.f;
    if (t < NN)           { g_deg[t] = 1; g_cur[t] = 0; }
}

// ---------------- fused lin0(+relu) and @Wc, 8 nodes per iter ---------------
__global__ void k_lin0(const float* __restrict__ x, const float* __restrict__ W0,
                       const float* __restrict__ b0, const float* __restrict__ Wc) {
    __shared__ float sW0[IND * DIM];
    __shared__ float sWc[DIM * DIM];
    __shared__ float sb0[DIM];
    __shared__ float sx[8][IND + 1];
    __shared__ float sh[8][DIM];
    int tid = threadIdx.x;                           // 256 threads
    for (int i = tid; i < IND * DIM; i += 256) sW0[i] = W0[i];
    for (int i = tid; i < DIM * DIM; i += 256) sWc[i] = Wc[i];
    if (tid < DIM) sb0[tid] = b0[tid];
    __syncthreads();
    int d = tid & 63, l0 = tid >> 6;                 // l0 in 0..3
    for (int base = blockIdx.x * 8; base < NN; base += gridDim.x * 8) {
        for (int i = tid; i < 8 * IND; i += 256) {
            int nn = i / IND, kk = i % IND;
            int node = base + nn;
            sx[nn][kk] = (node < NN) ? x[node * IND + kk] : 0.f;
        }
        __syncthreads();
        #pragma unroll
        for (int ln = l0; ln < 8; ln += 4) {
            float acc = sb0[d];
            #pragma unroll
            for (int k = 0; k < IND; k++) acc += sx[ln][k] * sW0[k * DIM + d];
            sh[ln][d] = fmaxf(acc, 0.f);
        }
        __syncthreads();
        #pragma unroll
        for (int ln = l0; ln < 8; ln += 4) {
            float acc2 = 0.f;
            #pragma unroll
            for (int k = 0; k < DIM; k++) acc2 += sh[ln][k] * sWc[k * DIM + d];
            int node = base + ln;
            if (node < NN) g_hw[node * DIM + d] = acc2;
        }
        __syncthreads();
    }
}

// ------ degree histogram + graph-range boundaries (batch is SORTED) ---------
__global__ void k_pre(const int* __restrict__ ei, const int* __restrict__ batch) {
    int t = blockIdx.x * 256 + threadIdx.x;
    if (t < NE) atomicAdd(&g_deg[ei[NE + t]], 1);
    if (t < NN) {
        int bt = batch[t];
        if (t == 0) {
            for (int g = 0; g <= bt; g++) g_goff[g] = 0;
        } else {
            int bp = batch[t - 1];
            for (int g = bp + 1; g <= bt; g++) g_goff[g] = t;
        }
        if (t == NN - 1) {
            for (int g = bt + 1; g <= NG; g++) g_goff[g] = NN;
        }
    }
}

// ------ scan phase 1: per-block sums of (deg-1) ------------------------------
__global__ void k_scan1() {
    __shared__ int sw[8];
    int t = blockIdx.x * 256 + threadIdx.x;
    int v = (t < NN) ? (g_deg[t] - 1) : 0;
    #pragma unroll
    for (int o = 16; o > 0; o >>= 1) v += __shfl_xor_sync(0xffffffffu, v, o);
    if ((threadIdx.x & 31) == 0) sw[threadIdx.x >> 5] = v;
    __syncthreads();
    if (threadIdx.x == 0) {
        int s = 0;
        #pragma unroll
        for (int w = 0; w < 8; w++) s += sw[w];
        g_bsum[blockIdx.x] = s;
    }
}

// ------ scan phase 2: exclusive scan of 196 block sums (one small block) ----
__global__ void k_scan2() {
    __shared__ int s[256];
    int t = threadIdx.x;
    s[t] = (t < SCAN_B) ? g_bsum[t] : 0;
    __syncthreads();
    #pragma unroll
    for (int off = 1; off < 256; off <<= 1) {
        int v = (t >= off) ? s[t - off] : 0;
        __syncthreads();
        s[t] += v;
        __syncthreads();
    }
    if (t < SCAN_B) g_boff[t] = t ? s[t - 1] : 0;
    if (t == 0) g_coff[NN] = s[SCAN_B - 1];
}

// ------ scan phase 3: in-block exclusive scan + base; fuse dinv --------------
__global__ void k_scan3() {
    __shared__ int s[256];
    int t = blockIdx.x * 256 + threadIdx.x;
    int tid = threadIdx.x;
    int dg = (t < NN) ? g_deg[t] : 1;
    int v = dg - 1;
    s[tid] = v;
    __syncthreads();
    #pragma unroll
    for (int off = 1; off < 256; off <<= 1) {
        int u = (tid >= off) ? s[tid - off] : 0;
        __syncthreads();
        s[tid] += u;
        __syncthreads();
    }
    if (t < NN) {
        g_coff[t] = g_boff[blockIdx.x] + s[tid] - v;   // exclusive
        g_dinv[t] = rsqrtf((float)dg);
    }
}

// ------ CSR placement: src list grouped by target ---------------------------
__global__ void k_place(const int* __restrict__ ei) {
    int t = blockIdx.x * 256 + threadIdx.x;
    if (t >= NE) return;
    int r = ei[t];
    int c = ei[NE + t];
    int pos = atomicAdd(&g_cur[c], 1);
    g_src[g_coff[c] + pos] = r;
}

// ------ gather (no atomics): h2 = relu(self + sum_in norm*hw[src] + bc) -----
// one warp per node; lane holds 2 dims (float2).
__global__ void k_gather(const float* __restrict__ bc) {
    int n = blockIdx.x * 8 + (threadIdx.x >> 5);
    if (n >= NN) return;
    int lane = threadIdx.x & 31;
    float dn = g_dinv[n];
    float2 hv = ((const float2*)g_hw)[n * 32 + lane];
    float s2 = dn * dn;
    float ax = s2 * hv.x, ay = s2 * hv.y;            // self-loop term
    int e0 = g_coff[n], e1 = g_coff[n + 1];
    for (int base = e0; base < e1; base += 32) {
        int m = min(32, e1 - base);
        int s = (lane < m) ? g_src[base + lane] : 0;
        for (int j = 0; j < m; j++) {
            int sj = __shfl_sync(0xffffffffu, s, j);
            float norm = g_dinv[sj] * dn;
            float2 v = ((const float2*)g_hw)[sj * 32 + lane];
            ax += norm * v.x;
            ay += norm * v.y;
        }
    }
    float2 b = ((const float2*)bc)[lane];
    float2 o;
    o.x = fmaxf(ax + b.x, 0.f);
    o.y = fmaxf(ay + b.y, 0.f);
    ((float2*)g_h2)[n * 32 + lane] = o;
}

// ---------------- LSTM gates: gates = qstar@Wih^T + hs@Whh^T + b -----------
__global__ void k_gates(const float* __restrict__ Wih, const float* __restrict__ Whh,
                        const float* __restrict__ bih, const float* __restrict__ bhh) {
    __shared__ float sq[32][129];
    __shared__ float shh[32][65];
    int g0 = blockIdx.x * 32;
    int j0 = blockIdx.y * 32;
    int tid = threadIdx.x;                           // 256
    for (int i = tid; i < 32 * 128; i += 256) {
        int g = i >> 7, k = i & 127;
        sq[g][k] = g_qstar[(g0 + g) * 128 + k];
    }
    for (int i = tid; i < 32 * 64; i += 256) {
        int g = i >> 6, k = i & 63;
        shh[g][k] = g_hs[(g0 + g) * 64 + k];
    }
    __syncthreads();
    int warp = tid >> 5, lane = tid & 31;            // lane = graph
    for (int jj = warp; jj < 32; jj += 8) {
        int j = j0 + jj;
        const float4* wi4 = (const float4*)(Wih + j * 128);
        const float2* wh2 = (const float2*)(Whh + j * 64);
        float acc = bih[j] + bhh[j];
        #pragma unroll
        for (int k4 = 0; k4 < 32; k4++) {
            float4 w = wi4[k4];
            acc += w.x * sq[lane][k4 * 4 + 0] + w.y * sq[lane][k4 * 4 + 1]
                 + w.z * sq[lane][k4 * 4 + 2] + w.w * sq[lane][k4 * 4 + 3];
        }
        #pragma unroll
        for (int k2 = 0; k2 < 32; k2++) {
            float2 w = wh2[k2];
            acc += w.x * shh[lane][k2 * 2 + 0] + w.y * shh[lane][k2 * 2 + 1];
        }
        g_gates[(g0 + lane) * 256 + j] = acc;
    }
}

// ------ fused LSTM cell + single-pass online-softmax attention --------------
// one block per graph, 128 threads (4 warps).
__global__ void k_attn() {
    int g = blockIdx.x;
    int tid = threadIdx.x;
    int warp = tid >> 5, lane = tid & 31;
    __shared__ float sqv[DIM];
    __shared__ float sm[4], ssm[4];
    __shared__ float sr[4][DIM];
    // LSTM cell for this graph (q = new h)
    if (tid < DIM) {
        const float* gt = g_gates + g * 256;
        float i = 1.f / (1.f + __expf(-gt[tid]));
        float f = 1.f / (1.f + __expf(-gt[64 + tid]));
        float gg = tanhf(gt[128 + tid]);
        float o = 1.f / (1.f + __expf(-gt[192 + tid]));
        float c = f * g_cs[g * DIM + tid] + i * gg;
        float h = o * tanhf(c);
        g_cs[g * DIM + tid] = c;
        g_hs[g * DIM + tid] = h;
        sqv[tid] = h;
    }
    __syncthreads();
    int start = g_goff[g], end = g_goff[g + 1];
    float q2x = sqv[lane * 2], q2y = sqv[lane * 2 + 1];
    // single pass: online softmax with warp-wide running max
    float m = -1e30f, wsum = 0.f, rx = 0.f, ry = 0.f;
    for (int v = start + warp; v < end; v += 4) {
        float2 hv = ((const float2*)g_h2)[v * 32 + lane];
        float d = hv.x * q2x + hv.y * q2y;
        d += __shfl_xor_sync(0xffffffffu, d, 16);
        d += __shfl_xor_sync(0xffffffffu, d, 8);
        d += __shfl_xor_sync(0xffffffffu, d, 4);
        d += __shfl_xor_sync(0xffffffffu, d, 2);
        d += __shfl_xor_sync(0xffffffffu, d, 1);
        float nm = fmaxf(m, d);
        float sc = __expf(m - nm);                   // 0 when m was -inf-ish
        float w = __expf(d - nm);
        wsum = wsum * sc + w;
        rx = rx * sc + w * hv.x;
        ry = ry * sc + w * hv.y;
        m = nm;
    }
    if (lane == 0) { sm[warp] = m; ssm[warp] = wsum; }
    sr[warp][lane * 2] = rx;
    sr[warp][lane * 2 + 1] = ry;
    __syncthreads();
    if (tid < DIM) {
        float M = fmaxf(fmaxf(sm[0], sm[1]), fmaxf(sm[2], sm[3]));
        float tot = 0.f, racc = 0.f;
        #pragma unroll
        for (int w = 0; w < 4; w++) {
            float e = __expf(sm[w] - M);
            tot += ssm[w] * e;
            racc += sr[w][tid] * e;
        }
        float r = (end > start) ? racc / tot : 0.f;  // empty graph -> r = 0
        g_qstar[g * 128 + tid] = sqv[tid];
        g_qstar[g * 128 + DIM + tid] = r;
    }
}

// ---------------- readout: relu(qstar@W1+b1)@W2 + b2 ------------------------
__global__ void k_readout(const float* __restrict__ W1, const float* __restrict__ b1,
                          const float* __restrict__ W2, const float* __restrict__ b2,
                          float* __restrict__ out) {
    int g = blockIdx.x;
    int d = threadIdx.x;                             // 64
    __shared__ float sq[128];
    __shared__ float red[64];
    sq[d] = g_qstar[g * 128 + d];
    sq[64 + d] = g_qstar[g * 128 + 64 + d];
    __syncthreads();
    float acc = b1[d];
    #pragma unroll
    for (int k = 0; k < 128; k++) acc += sq[k] * W1[k * 64 + d];
    acc = fmaxf(acc, 0.f) * W2[d];
    red[d] = acc;
    __syncthreads();
    for (int s = 32; s > 0; s >>= 1) {
        if (d < s) red[d] += red[d + s];
        __syncthreads();
    }
    if (d == 0) out[g] = red[0] + b2[0];
}

// ---------------- launch sequence -------------------------------------------
extern "C" void kernel_launch(void* const* d_in, const int* in_sizes, int n_in,
                              void* d_out, int out_size) {
    const float* x     = (const float*)d_in[0];
    const int*   ei    = (const int*)  d_in[1];
    const int*   batch = (const int*)  d_in[2];
    const float* W0    = (const float*)d_in[3];
    const float* b0    = (const float*)d_in[4];
    const float* Wc    = (const float*)d_in[5];
    const float* bc    = (const float*)d_in[6];
    const float* Wih   = (const float*)d_in[7];
    const float* Whh   = (const float*)d_in[8];
    const float* bih   = (const float*)d_in[9];
    const float* bhh   = (const float*)d_in[10];
    const float* W1    = (const float*)d_in[11];
    const float* b1    = (const float*)d_in[12];
    const float* W2    = (const float*)d_in[13];
    const float* b2    = (const float*)d_in[14];
    float* out = (float*)d_out;

    k_init<<<512, 256>>>();
    k_lin0<<<512, 256>>>(x, W0, b0, Wc);
    k_pre<<<(NE + 255) / 256, 256>>>(ei, batch);
    k_scan1<<<SCAN_B, 256>>>();
    k_scan2<<<1, 256>>>();
    k_scan3<<<SCAN_B, 256>>>();
    k_place<<<(NE + 255) / 256, 256>>>(ei);
    k_gather<<<(NN + 7) / 8, 256>>>(bc);
    for (int s = 0; s < STEPS; s++) {
        k_gates<<<dim3(32, 8), 256>>>(Wih, Whh, bih, bhh);
        k_attn<<<NG, 128>>>();
    }
    k_readout<<<NG, 64>>>(W1, b1, W2, b2, out);
}

// round 7
// speedup vs baseline: 1.5082x; 1.0961x over previous
#include <cuda_runtime.h>
#include <math.h>

#define NN 50000
#define NE 800000
#define NG 1024
#define IND 25
#define DIM 64
#define STEPS 3
#define SCAN_B 196                     // ceil(NN/256)

// ---------------- device scratch (statically allocated; no cudaMalloc) ------
__device__ float g_hw[NN * DIM];      // relu(x@W0+b0) @ Wc
__device__ float g_h2[NN * DIM];      // relu(agg + bc)  -> set2set input
__device__ float g_dinv[NN];
__device__ int   g_deg[NN];           // degree incl. self loop
__device__ int   g_cur[NN];           // placement cursors
__device__ int   g_coff[NN + 1];      // CSR offsets (in-edges, excl. self)
__device__ int   g_src[NE];           // CSR source list
__device__ int   g_goff[NG + 1];      // per-graph node ranges (batch sorted)
__device__ int   g_bsum[SCAN_B];      // per-block partial sums
__device__ float g_wc2[256 * DIM];    // Wih[:, :64] + Whh  (precombined)

// ---------------- init: deg=1 (self loop), cursors, total offset ------------
__global__ void k_init() {
    int t = blockIdx.x * 256 + threadIdx.x;
    if (t < NN) { g_deg[t] = 1; g_cur[t] = 0; }
    if (t == 0) g_coff[NN] = NE;      // sum(deg-1) == NE identically
}

// ---------------- precombine LSTM weights: wc2 = Wih[:, :64] + Whh ----------
__global__ void k_prew(const float* __restrict__ Wih, const float* __restrict__ Whh) {
    int t = blockIdx.x * 256 + threadIdx.x;        // 256*64 = 16384
    if (t >= 256 * DIM) return;
    int j = t >> 6, k = t & 63;
    g_wc2[t] = Wih[j * 128 + k] + Whh[t];
}

// ---------------- fused lin0(+relu) and @Wc, 8 nodes per iter ---------------
__global__ void k_lin0(const float* __restrict__ x, const float* __restrict__ W0,
                       const float* __restrict__ b0, const float* __restrict__ Wc) {
    __shared__ float sW0[IND * DIM];
    __shared__ float sWc[DIM * DIM];
    __shared__ float sb0[DIM];
    __shared__ float sx[8][IND + 1];
    __shared__ float sh[8][DIM];
    int tid = threadIdx.x;                           // 256 threads
    for (int i = tid; i < IND * DIM; i += 256) sW0[i] = W0[i];
    for (int i = tid; i < DIM * DIM; i += 256) sWc[i] = Wc[i];
    if (tid < DIM) sb0[tid] = b0[tid];
    __syncthreads();
    int d = tid & 63, l0 = tid >> 6;                 // l0 in 0..3
    for (int base = blockIdx.x * 8; base < NN; base += gridDim.x * 8) {
        for (int i = tid; i < 8 * IND; i += 256) {
            int nn = i / IND, kk = i % IND;
            int node = base + nn;
            sx[nn][kk] = (node < NN) ? x[node * IND + kk] : 0.f;
        }
        __syncthreads();
        #pragma unroll
        for (int ln = l0; ln < 8; ln += 4) {
            float acc = sb0[d];
            #pragma unroll
            for (int k = 0; k < IND; k++) acc += sx[ln][k] * sW0[k * DIM + d];
            sh[ln][d] = fmaxf(acc, 0.f);
        }
        __syncthreads();
        #pragma unroll
        for (int ln = l0; ln < 8; ln += 4) {
            float acc2 = 0.f;
            #pragma unroll
            for (int k = 0; k < DIM; k++) acc2 += sh[ln][k] * sWc[k * DIM + d];
            int node = base + ln;
            if (node < NN) g_hw[node * DIM + d] = acc2;
        }
        __syncthreads();
    }
}

// ------ degree histogram + graph-range boundaries (batch is SORTED) ---------
__global__ void k_pre(const int* __restrict__ ei, const int* __restrict__ batch) {
    int t = blockIdx.x * 256 + threadIdx.x;
    if (t < NE) atomicAdd(&g_deg[ei[NE + t]], 1);
    if (t < NN) {
        int bt = batch[t];
        if (t == 0) {
            for (int g = 0; g <= bt; g++) g_goff[g] = 0;
        } else {
            int bp = batch[t - 1];
            for (int g = bp + 1; g <= bt; g++) g_goff[g] = t;
        }
        if (t == NN - 1) {
            for (int g = bt + 1; g <= NG; g++) g_goff[g] = NN;
        }
    }
}

// ------ scan phase 1: per-block sums of (deg-1) ------------------------------
__global__ void k_scan1() {
    __shared__ int sw[8];
    int t = blockIdx.x * 256 + threadIdx.x;
    int v = (t < NN) ? (g_deg[t] - 1) : 0;
    #pragma unroll
    for (int o = 16; o > 0; o >>= 1) v += __shfl_xor_sync(0xffffffffu, v, o);
    if ((threadIdx.x & 31) == 0) sw[threadIdx.x >> 5] = v;
    __syncthreads();
    if (threadIdx.x == 0) {
        int s = 0;
        #pragma unroll
        for (int w = 0; w < 8; w++) s += sw[w];
        g_bsum[blockIdx.x] = s;
    }
}

// ------ scan phase 2+3: block base via local 196-scan, in-block scan, dinv --
__global__ void k_scan3() {
    __shared__ int sb[256];
    __shared__ int s[256];
    int tid = threadIdx.x;
    int t = blockIdx.x * 256 + tid;
    sb[tid] = (tid < SCAN_B) ? g_bsum[tid] : 0;
    int dg = (t < NN) ? g_deg[t] : 1;
    int v = dg - 1;
    s[tid] = v;
    __syncthreads();
    #pragma unroll
    for (int off = 1; off < 256; off <<= 1) {
        int u  = (tid >= off) ? s[tid - off]  : 0;
        int ub = (tid >= off) ? sb[tid - off] : 0;
        __syncthreads();
        s[tid] += u;
        sb[tid] += ub;
        __syncthreads();
    }
    if (t < NN) {
        int base = blockIdx.x ? sb[blockIdx.x - 1] : 0;
        g_coff[t] = base + s[tid] - v;               // exclusive
        g_dinv[t] = rsqrtf((float)dg);
    }
}

// ------ CSR placement: src list grouped by target ---------------------------
__global__ void k_place(const int* __restrict__ ei) {
    int t = blockIdx.x * 256 + threadIdx.x;
    if (t >= NE) return;
    int r = ei[t];
    int c = ei[NE + t];
    int pos = atomicAdd(&g_cur[c], 1);
    g_src[g_coff[c] + pos] = r;
}

// ------ gather (no atomics): h2 = relu(self + sum_in norm*hw[src] + bc) -----
// one warp per node; lane holds 2 dims (float2).
__global__ void k_gather(const float* __restrict__ bc) {
    int n = blockIdx.x * 8 + (threadIdx.x >> 5);
    if (n >= NN) return;
    int lane = threadIdx.x & 31;
    float dn = g_dinv[n];
    float2 hv = ((const float2*)g_hw)[n * 32 + lane];
    float s2 = dn * dn;
    float ax = s2 * hv.x, ay = s2 * hv.y;            // self-loop term
    int e0 = g_coff[n], e1 = g_coff[n + 1];
    for (int base = e0; base < e1; base += 32) {
        int m = min(32, e1 - base);
        int s = (lane < m) ? g_src[base + lane] : 0;
        for (int j = 0; j < m; j++) {
            int sj = __shfl_sync(0xffffffffu, s, j);
            float norm = g_dinv[sj] * dn;
            float2 v = ((const float2*)g_hw)[sj * 32 + lane];
            ax += norm * v.x;
            ay += norm * v.y;
        }
    }
    float2 b = ((const float2*)bc)[lane];
    float2 o;
    o.x = fmaxf(ax + b.x, 0.f);
    o.y = fmaxf(ay + b.y, 0.f);
    ((float2*)g_h2)[n * 32 + lane] = o;
}

// ------ fully fused Set2Set: 3 x (gates + LSTM cell + attention) + readout --
// one block per graph, 128 threads (4 warps). All state lives in shared.
__global__ void k_s2s(const float* __restrict__ Wih,
                      const float* __restrict__ bih, const float* __restrict__ bhh,
                      const float* __restrict__ W1, const float* __restrict__ b1,
                      const float* __restrict__ W2, const float* __restrict__ b2,
                      float* __restrict__ out) {
    int g = blockIdx.x;
    int tid = threadIdx.x;
    int warp = tid >> 5, lane = tid & 31;
    __shared__ __align__(16) float s_h[DIM];   // current h (== q)
    __shared__ __align__(16) float s_c[DIM];
    __shared__ __align__(16) float s_r[DIM];
    __shared__ float s_gate[256];
    __shared__ float sm[4], ssm[4];
    __shared__ float sr[4][DIM];
    __shared__ float red[DIM];

    int start = g_goff[g], end = g_goff[g + 1];
    float bsum0 = bih[tid] + bhh[tid];
    float bsum1 = bih[tid + 128] + bhh[tid + 128];
    if (tid < DIM) { s_c[tid] = 0.f; s_r[tid] = 0.f; s_h[tid] = 0.f; }
    __syncthreads();

    for (int step = 0; step < STEPS; step++) {
        // ---- gates: rows tid and tid+128 ----
        float acc0 = bsum0, acc1 = bsum1;
        if (step > 0) {
            const float4* sh4 = (const float4*)s_h;
            const float4* sr4 = (const float4*)s_r;
            const float4* w0 = (const float4*)(g_wc2 + tid * DIM);
            const float4* w1 = (const float4*)(g_wc2 + (tid + 128) * DIM);
            const float4* u0 = (const float4*)(Wih + tid * 128 + 64);
            const float4* u1 = (const float4*)(Wih + (tid + 128) * 128 + 64);
            #pragma unroll
            for (int k = 0; k < 16; k++) {
                float4 hv = sh4[k], rv = sr4[k];
                float4 a = w0[k], b = u0[k], c = w1[k], d = u1[k];
                acc0 += a.x * hv.x + a.y * hv.y + a.z * hv.z + a.w * hv.w
                      + b.x * rv.x + b.y * rv.y + b.z * rv.z + b.w * rv.w;
                acc1 += c.x * hv.x + c.y * hv.y + c.z * hv.z + c.w * hv.w
                      + d.x * rv.x + d.y * rv.y + d.z * rv.z + d.w * rv.w;
            }
        }
        s_gate[tid] = acc0;
        s_gate[tid + 128] = acc1;
        __syncthreads();
        // ---- LSTM cell ----
        if (tid < DIM) {
            float i = 1.f / (1.f + __expf(-s_gate[tid]));
            float f = 1.f / (1.f + __expf(-s_gate[64 + tid]));
            float gg = tanhf(s_gate[128 + tid]);
            float o = 1.f / (1.f + __expf(-s_gate[192 + tid]));
            float c = f * s_c[tid] + i * gg;
            s_c[tid] = c;
            s_h[tid] = o * tanhf(c);
        }
        __syncthreads();
        // ---- attention: single-pass online softmax over this graph's nodes --
        float q2x = s_h[lane * 2], q2y = s_h[lane * 2 + 1];
        float m = -1e30f, wsum = 0.f, rx = 0.f, ry = 0.f;
        for (int v = start + warp; v < end; v += 4) {
            float2 hv = ((const float2*)g_h2)[v * 32 + lane];
            float d = hv.x * q2x + hv.y * q2y;
            d += __shfl_xor_sync(0xffffffffu, d, 16);
            d += __shfl_xor_sync(0xffffffffu, d, 8);
            d += __shfl_xor_sync(0xffffffffu, d, 4);
            d += __shfl_xor_sync(0xffffffffu, d, 2);
            d += __shfl_xor_sync(0xffffffffu, d, 1);
            float nm = fmaxf(m, d);
            float sc = __expf(m - nm);
            float w = __expf(d - nm);
            wsum = wsum * sc + w;
            rx = rx * sc + w * hv.x;
            ry = ry * sc + w * hv.y;
            m = nm;
        }
        if (lane == 0) { sm[warp] = m; ssm[warp] = wsum; }
        sr[warp][lane * 2] = rx;
        sr[warp][lane * 2 + 1] = ry;
        __syncthreads();
        if (tid < DIM) {
            float M = fmaxf(fmaxf(sm[0], sm[1]), fmaxf(sm[2], sm[3]));
            float tot = 0.f, racc = 0.f;
            #pragma unroll
            for (int w = 0; w < 4; w++) {
                float e = __expf(sm[w] - M);
                tot += ssm[w] * e;
                racc += sr[w][tid] * e;
            }
            s_r[tid] = (end > start) ? racc / tot : 0.f;
        }
        __syncthreads();
    }
    // ---- readout: relu([h, r] @ W1 + b1) @ W2 + b2 ----
    if (tid < DIM) {
        float acc = b1[tid];
        #pragma unroll
        for (int k = 0; k < DIM; k++) acc += s_h[k] * W1[k * 64 + tid];
        #pragma unroll
        for (int k = 0; k < DIM; k++) acc += s_r[k] * W1[(64 + k) * 64 + tid];
        acc = fmaxf(acc, 0.f) * W2[tid];
        // warp reduce (two warps of tid<64)
        #pragma unroll
        for (int o = 16; o > 0; o >>= 1) acc += __shfl_xor_sync(0xffffffffu, acc, o);
        if (lane == 0) red[warp] = acc;
    }
    __syncthreads();
    if (tid == 0) out[g] = red[0] + red[1] + b2[0];
}

// ---------------- launch sequence -------------------------------------------
extern "C" void kernel_launch(void* const* d_in, const int* in_sizes, int n_in,
                              void* d_out, int out_size) {
    const float* x     = (const float*)d_in[0];
    const int*   ei    = (const int*)  d_in[1];
    const int*   batch = (const int*)  d_in[2];
    const float* W0    = (const float*)d_in[3];
    const float* b0    = (const float*)d_in[4];
    const float* Wc    = (const float*)d_in[5];
    const float* bc    = (const float*)d_in[6];
    const float* Wih   = (const float*)d_in[7];
    const float* Whh   = (const float*)d_in[8];
    const float* bih   = (const float*)d_in[9];
    const float* bhh   = (const float*)d_in[10];
    const float* W1    = (const float*)d_in[11];
    const float* b1    = (const float*)d_in[12];
    const float* W2    = (const float*)d_in[13];
    const float* b2    = (const float*)d_in[14];
    float* out = (float*)d_out;

    k_init<<<SCAN_B, 256>>>();
    k_prew<<<64, 256>>>(Wih, Whh);
    k_lin0<<<512, 256>>>(x, W0, b0, Wc);
    k_pre<<<(NE + 255) / 256, 256>>>(ei, batch);
    k_scan1<<<SCAN_B, 256>>>();
    k_scan3<<<SCAN_B, 256>>>();
    k_place<<<(NE + 255) / 256, 256>>>(ei);
    k_gather<<<(NN + 7) / 8, 256>>>(bc);
    k_s2s<<<NG, 128>>>(Wih, bih, bhh, W1, b1, W2, b2, out);
}

// round 8
// speedup vs baseline: 1.5202x; 1.0080x over previous
#include <cuda_runtime.h>
#include <math.h>

#define NN 50000
#define NE 800000
#define NG 1024
#define IND 25
#define DIM 64
#define STEPS 3
#define SCAN_B 196                     // ceil(NN/256)

// ---------------- device scratch (statically allocated; no cudaMalloc) ------
__device__ float g_hw[NN * DIM];      // dinv[n] * (relu(x@W0+b0) @ Wc)   (pre-scaled!)
__device__ float g_h2[NN * DIM];      // relu(agg + bc)  -> set2set input
__device__ float g_dinv[NN];
__device__ int   g_deg[NN];           // degree incl. self loop
__device__ int   g_cur[NN];           // placement cursors
__device__ int   g_coff[NN + 1];      // CSR offsets (in-edges, excl. self)
__device__ int   g_src[NE];           // CSR source list
__device__ int   g_goff[NG + 1];      // per-graph node ranges (batch sorted)
__device__ int   g_bsum[SCAN_B];      // per-block partial sums
__device__ float g_wc2[256 * DIM];    // Wih[:, :64] + Whh  (precombined)

// ------ init: deg=1, cursors, coff[NN], and precombined LSTM weights --------
__global__ void k_init(const float* __restrict__ Wih, const float* __restrict__ Whh) {
    int t = blockIdx.x * 256 + threadIdx.x;
    if (t < NN) { g_deg[t] = 1; g_cur[t] = 0; }
    if (t < 256 * DIM) {
        int j = t >> 6, k = t & 63;
        g_wc2[t] = Wih[j * 128 + k] + Whh[t];
    }
    if (t == 0) g_coff[NN] = NE;      // sum(deg-1) == NE identically
}

// ------ degree histogram + graph-range boundaries (batch is SORTED) ---------
__global__ void k_pre(const int* __restrict__ ei, const int* __restrict__ batch) {
    int t = blockIdx.x * 256 + threadIdx.x;
    if (t < NE) atomicAdd(&g_deg[ei[NE + t]], 1);
    if (t < NN) {
        int bt = batch[t];
        if (t == 0) {
            for (int g = 0; g <= bt; g++) g_goff[g] = 0;
        } else {
            int bp = batch[t - 1];
            for (int g = bp + 1; g <= bt; g++) g_goff[g] = t;
        }
        if (t == NN - 1) {
            for (int g = bt + 1; g <= NG; g++) g_goff[g] = NN;
        }
    }
}

// ------ scan phase 1: per-block sums of (deg-1) ------------------------------
__global__ void k_scan1() {
    __shared__ int sw[8];
    int t = blockIdx.x * 256 + threadIdx.x;
    int v = (t < NN) ? (g_deg[t] - 1) : 0;
    #pragma unroll
    for (int o = 16; o > 0; o >>= 1) v += __shfl_xor_sync(0xffffffffu, v, o);
    if ((threadIdx.x & 31) == 0) sw[threadIdx.x >> 5] = v;
    __syncthreads();
    if (threadIdx.x == 0) {
        int s = 0;
        #pragma unroll
        for (int w = 0; w < 8; w++) s += sw[w];
        g_bsum[blockIdx.x] = s;
    }
}

// ------ scan phase 2+3: block base via local 196-scan, in-block scan, dinv --
__global__ void k_scan3() {
    __shared__ int sb[256];
    __shared__ int s[256];
    int tid = threadIdx.x;
    int t = blockIdx.x * 256 + tid;
    sb[tid] = (tid < SCAN_B) ? g_bsum[tid] : 0;
    int dg = (t < NN) ? g_deg[t] : 1;
    int v = dg - 1;
    s[tid] = v;
    __syncthreads();
    #pragma unroll
    for (int off = 1; off < 256; off <<= 1) {
        int u  = (tid >= off) ? s[tid - off]  : 0;
        int ub = (tid >= off) ? sb[tid - off] : 0;
        __syncthreads();
        s[tid] += u;
        sb[tid] += ub;
        __syncthreads();
    }
    if (t < NN) {
        int base = blockIdx.x ? sb[blockIdx.x - 1] : 0;
        g_coff[t] = base + s[tid] - v;               // exclusive
        g_dinv[t] = rsqrtf((float)dg);
    }
}

// ---- fused lin0(+relu), @Wc, and dinv pre-scale; 8 nodes per iter -----------
__global__ void k_lin0(const float* __restrict__ x, const float* __restrict__ W0,
                       const float* __restrict__ b0, const float* __restrict__ Wc) {
    __shared__ float sW0[IND * DIM];
    __shared__ float sWc[DIM * DIM];
    __shared__ float sb0[DIM];
    __shared__ float sx[8][IND + 1];
    __shared__ float sh[8][DIM];
    int tid = threadIdx.x;                           // 256 threads
    for (int i = tid; i < IND * DIM; i += 256) sW0[i] = W0[i];
    for (int i = tid; i < DIM * DIM; i += 256) sWc[i] = Wc[i];
    if (tid < DIM) sb0[tid] = b0[tid];
    __syncthreads();
    int d = tid & 63, l0 = tid >> 6;                 // l0 in 0..3
    for (int base = blockIdx.x * 8; base < NN; base += gridDim.x * 8) {
        for (int i = tid; i < 8 * IND; i += 256) {
            int nn = i / IND, kk = i % IND;
            int node = base + nn;
            sx[nn][kk] = (node < NN) ? x[node * IND + kk] : 0.f;
        }
        __syncthreads();
        #pragma unroll
        for (int ln = l0; ln < 8; ln += 4) {
            float acc = sb0[d];
            #pragma unroll
            for (int k = 0; k < IND; k++) acc += sx[ln][k] * sW0[k * DIM + d];
            sh[ln][d] = fmaxf(acc, 0.f);
        }
        __syncthreads();
        #pragma unroll
        for (int ln = l0; ln < 8; ln += 4) {
            float acc2 = 0.f;
            #pragma unroll
            for (int k = 0; k < DIM; k++) acc2 += sh[ln][k] * sWc[k * DIM + d];
            int node = base + ln;
            if (node < NN) g_hw[node * DIM + d] = acc2 * g_dinv[node];
        }
        __syncthreads();
    }
}

// ------ CSR placement: src list grouped by target ---------------------------
__global__ void k_place(const int* __restrict__ ei) {
    int t = blockIdx.x * 256 + threadIdx.x;
    if (t >= NE) return;
    int r = ei[t];
    int c = ei[NE + t];
    int pos = atomicAdd(&g_cur[c], 1);
    g_src[g_coff[c] + pos] = r;
}

// ------ gather (no atomics): h2 = relu(dn*(hw'[n] + sum hw'[src]) + bc) -----
// 16 lanes per node (float4), 2 nodes per warp, 4-way unrolled neighbor loop.
__global__ void k_gather(const float* __restrict__ bc) {
    int warp_id = blockIdx.x * 8 + (threadIdx.x >> 5);
    int lane = threadIdx.x & 31;
    int half = lane >> 4, hl = lane & 15;
    int n = warp_id * 2 + half;
    if (n >= NN) return;
    unsigned hmask = half ? 0xffff0000u : 0x0000ffffu;
    const float4* hw4 = (const float4*)g_hw;
    float dn = g_dinv[n];
    float4 acc = hw4[n * 16 + hl];                   // self term (hw pre-scaled)
    int e0 = g_coff[n], e1 = g_coff[n + 1];
    for (int base = e0; base < e1; base += 16) {
        int m = min(16, e1 - base);
        int s = (hl < m) ? g_src[base + hl] : 0;
        int j = 0;
        for (; j + 4 <= m; j += 4) {
            int s0 = __shfl_sync(hmask, s, j,     16);
            int s1 = __shfl_sync(hmask, s, j + 1, 16);
            int s2 = __shfl_sync(hmask, s, j + 2, 16);
            int s3 = __shfl_sync(hmask, s, j + 3, 16);
            float4 v0 = hw4[s0 * 16 + hl];
            float4 v1 = hw4[s1 * 16 + hl];
            float4 v2 = hw4[s2 * 16 + hl];
            float4 v3 = hw4[s3 * 16 + hl];
            acc.x += (v0.x + v1.x) + (v2.x + v3.x);
            acc.y += (v0.y + v1.y) + (v2.y + v3.y);
            acc.z += (v0.z + v1.z) + (v2.z + v3.z);
            acc.w += (v0.w + v1.w) + (v2.w + v3.w);
        }
        for (; j < m; j++) {
            int sj = __shfl_sync(hmask, s, j, 16);
            float4 v = hw4[sj * 16 + hl];
            acc.x += v.x; acc.y += v.y; acc.z += v.z; acc.w += v.w;
        }
    }
    float4 b = ((const float4*)bc)[hl];
    float4 o;
    o.x = fmaxf(dn * acc.x + b.x, 0.f);
    o.y = fmaxf(dn * acc.y + b.y, 0.f);
    o.z = fmaxf(dn * acc.z + b.z, 0.f);
    o.w = fmaxf(dn * acc.w + b.w, 0.f);
    ((float4*)g_h2)[n * 16 + hl] = o;
}

// ------ fully fused Set2Set: 3 x (gates + LSTM cell + attention) + readout --
// one block per graph, 128 threads (4 warps). All state lives in shared.
__global__ void k_s2s(const float* __restrict__ Wih,
                      const float* __restrict__ bih, const float* __restrict__ bhh,
                      const float* __restrict__ W1, const float* __restrict__ b1,
                      const float* __restrict__ W2, const float* __restrict__ b2,
                      float* __restrict__ out) {
    int g = blockIdx.x;
    int tid = threadIdx.x;
    int warp = tid >> 5, lane = tid & 31;
    __shared__ __align__(16) float s_h[DIM];   // current h (== q)
    __shared__ __align__(16) float s_c[DIM];
    __shared__ __align__(16) float s_r[DIM];
    __shared__ float s_gate[256];
    __shared__ float sm[4], ssm[4];
    __shared__ float sr[4][DIM];
    __shared__ float red[DIM];

    int start = g_goff[g], end = g_goff[g + 1];
    float bsum0 = bih[tid] + bhh[tid];
    float bsum1 = bih[tid + 128] + bhh[tid + 128];
    if (tid < DIM) { s_c[tid] = 0.f; s_r[tid] = 0.f; s_h[tid] = 0.f; }
    __syncthreads();

    for (int step = 0; step < STEPS; step++) {
        // ---- gates: rows tid and tid+128 ----
        float acc0 = bsum0, acc1 = bsum1;
        if (step > 0) {
            const float4* sh4 = (const float4*)s_h;
            const float4* sr4 = (const float4*)s_r;
            const float4* w0 = (const float4*)(g_wc2 + tid * DIM);
            const float4* w1 = (const float4*)(g_wc2 + (tid + 128) * DIM);
            const float4* u0 = (const float4*)(Wih + tid * 128 + 64);
            const float4* u1 = (const float4*)(Wih + (tid + 128) * 128 + 64);
            #pragma unroll
            for (int k = 0; k < 16; k++) {
                float4 hv = sh4[k], rv = sr4[k];
                float4 a = w0[k], b = u0[k], c = w1[k], d = u1[k];
                acc0 += a.x * hv.x + a.y * hv.y + a.z * hv.z + a.w * hv.w
                      + b.x * rv.x + b.y * rv.y + b.z * rv.z + b.w * rv.w;
                acc1 += c.x * hv.x + c.y * hv.y + c.z * hv.z + c.w * hv.w
                      + d.x * rv.x + d.y * rv.y + d.z * rv.z + d.w * rv.w;
            }
        }
        s_gate[tid] = acc0;
        s_gate[tid + 128] = acc1;
        __syncthreads();
        // ---- LSTM cell ----
        if (tid < DIM) {
            float i = 1.f / (1.f + __expf(-s_gate[tid]));
            float f = 1.f / (1.f + __expf(-s_gate[64 + tid]));
            float gg = tanhf(s_gate[128 + tid]);
            float o = 1.f / (1.f + __expf(-s_gate[192 + tid]));
            float c = f * s_c[tid] + i * gg;
            s_c[tid] = c;
            s_h[tid] = o * tanhf(c);
        }
        __syncthreads();
        // ---- attention: dual-stream online softmax over this graph's nodes --
        float q2x = s_h[lane * 2], q2y = s_h[lane * 2 + 1];
        float m0 = -1e30f, ws0 = 0.f, rx0 = 0.f, ry0 = 0.f;
        float m1 = -1e30f, ws1 = 0.f, rx1 = 0.f, ry1 = 0.f;
        for (int v = start + warp; v < end; v += 8) {
            int v2 = v + 4;
            bool has1 = (v2 < end);
            float2 hva = ((const float2*)g_h2)[v * 32 + lane];
            float2 hvb = has1 ? ((const float2*)g_h2)[v2 * 32 + lane]
                              : make_float2(0.f, 0.f);
            float da = hva.x * q2x + hva.y * q2y;
            float db = hvb.x * q2x + hvb.y * q2y;
            #pragma unroll
            for (int o = 16; o > 0; o >>= 1) {
                da += __shfl_xor_sync(0xffffffffu, da, o);
                db += __shfl_xor_sync(0xffffffffu, db, o);
            }
            {
                float nm = fmaxf(m0, da);
                float sc = __expf(m0 - nm);
                float w = __expf(da - nm);
                ws0 = ws0 * sc + w;
                rx0 = rx0 * sc + w * hva.x;
                ry0 = ry0 * sc + w * hva.y;
                m0 = nm;
            }
            if (has1) {
                float nm = fmaxf(m1, db);
                float sc = __expf(m1 - nm);
                float w = __expf(db - nm);
                ws1 = ws1 * sc + w;
                rx1 = rx1 * sc + w * hvb.x;
                ry1 = ry1 * sc + w * hvb.y;
                m1 = nm;
            }
        }
        // merge streams
        float m = fmaxf(m0, m1);
        float e0 = __expf(m0 - m), e1 = __expf(m1 - m);
        float wsum = ws0 * e0 + ws1 * e1;
        float rx = rx0 * e0 + rx1 * e1;
        float ry = ry0 * e0 + ry1 * e1;
        if (lane == 0) { sm[warp] = m; ssm[warp] = wsum; }
        sr[warp][lane * 2] = rx;
        sr[warp][lane * 2 + 1] = ry;
        __syncthreads();
        if (tid < DIM) {
            float M = fmaxf(fmaxf(sm[0], sm[1]), fmaxf(sm[2], sm[3]));
            float tot = 0.f, racc = 0.f;
            #pragma unroll
            for (int w = 0; w < 4; w++) {
                float e = __expf(sm[w] - M);
                tot += ssm[w] * e;
                racc += sr[w][tid] * e;
            }
            s_r[tid] = (end > start) ? racc / tot : 0.f;
        }
        __syncthreads();
    }
    // ---- readout: relu([h, r] @ W1 + b1) @ W2 + b2 ----
    if (tid < DIM) {
        float acc = b1[tid];
        #pragma unroll
        for (int k = 0; k < DIM; k++) acc += s_h[k] * W1[k * 64 + tid];
        #pragma unroll
        for (int k = 0; k < DIM; k++) acc += s_r[k] * W1[(64 + k) * 64 + tid];
        acc = fmaxf(acc, 0.f) * W2[tid];
        #pragma unroll
        for (int o = 16; o > 0; o >>= 1) acc += __shfl_xor_sync(0xffffffffu, acc, o);
        if (lane == 0) red[warp] = acc;
    }
    __syncthreads();
    if (tid == 0) out[g] = red[0] + red[1] + b2[0];
}

// ---------------- launch sequence -------------------------------------------
extern "C" void kernel_launch(void* const* d_in, const int* in_sizes, int n_in,
                              void* d_out, int out_size) {
    const float* x     = (const float*)d_in[0];
    const int*   ei    = (const int*)  d_in[1];
    const int*   batch = (const int*)  d_in[2];
    const float* W0    = (const float*)d_in[3];
    const float* b0    = (const float*)d_in[4];
    const float* Wc    = (const float*)d_in[5];
    const float* bc    = (const float*)d_in[6];
    const float* Wih   = (const float*)d_in[7];
    const float* Whh   = (const float*)d_in[8];
    const float* bih   = (const float*)d_in[9];
    const float* bhh   = (const float*)d_in[10];
    const float* W1    = (const float*)d_in[11];
    const float* b1    = (const float*)d_in[12];
    const float* W2    = (const float*)d_in[13];
    const float* b2    = (const float*)d_in[14];
    float* out = (float*)d_out;

    k_init<<<SCAN_B, 256>>>(Wih, Whh);
    k_pre<<<(NE + 255) / 256, 256>>>(ei, batch);
    k_scan1<<<SCAN_B, 256>>>();
    k_scan3<<<SCAN_B, 256>>>();
    k_lin0<<<512, 256>>>(x, W0, b0, Wc);
    k_place<<<(NE + 255) / 256, 256>>>(ei);
    k_gather<<<(NN / 2 + 7) / 8, 256>>>(bc);
    k_s2s<<<NG, 128>>>(Wih, bih, bhh, W1, b1, W2, b2, out);
}

// round 9
// speedup vs baseline: 2.0745x; 1.3646x over previous
#include <cuda_runtime.h>
#include <math.h>

#define NN 50000
#define NE 800000
#define NG 1024
#define IND 25
#define DIM 64
#define STEPS 3
#define SCAN_B 196                     // ceil(NN/256)

// ---------------- device scratch (statically allocated; no cudaMalloc) ------
__device__ float g_hw[NN * DIM];      // dinv[n] * (relu(x@W0+b0) @ Wc)   (pre-scaled!)
__device__ float g_h2[NN * DIM];      // relu(agg + bc)  -> set2set input
__device__ float g_dinv[NN];
__device__ int   g_deg[NN];           // degree incl. self loop
__device__ int   g_cur[NN];           // placement cursors
__device__ int   g_coff[NN + 1];      // CSR offsets (in-edges, excl. self)
__device__ int   g_src[NE];           // CSR source list
__device__ int   g_goff[NG + 1];      // per-graph node ranges (batch sorted)
__device__ int   g_bsum[SCAN_B];      // per-block partial sums
// Transposed+packed gate weights: Q[k2*128 + j] =
//   { W(j,2k2), W(j+128,2k2), W(j,2k2+1), W(j+128,2k2+1) },
//   W(row,k) = Wih[row][k] + (k<64 ? Whh[row][k] : 0)
__device__ float4 g_Q[64 * 128];

// ------ init: deg=1, cursors, coff[NN], transposed gate weights -------------
__global__ void k_init(const float* __restrict__ Wih, const float* __restrict__ Whh) {
    int t = blockIdx.x * 256 + threadIdx.x;
    if (t < NN) { g_deg[t] = 1; g_cur[t] = 0; }
    if (t < 64 * 128) {
        int j = t & 127, k2 = t >> 7;
        int k0 = 2 * k2, k1 = k0 + 1;
        float4 q;
        q.x = Wih[j * 128 + k0]         + (k0 < 64 ? Whh[j * 64 + k0] : 0.f);
        q.y = Wih[(j + 128) * 128 + k0] + (k0 < 64 ? Whh[(j + 128) * 64 + k0] : 0.f);
        q.z = Wih[j * 128 + k1]         + (k1 < 64 ? Whh[j * 64 + k1] : 0.f);
        q.w = Wih[(j + 128) * 128 + k1] + (k1 < 64 ? Whh[(j + 128) * 64 + k1] : 0.f);
        g_Q[t] = q;
    }
    if (t == 0) g_coff[NN] = NE;      // sum(deg-1) == NE identically
}

// ------ degree histogram + graph-range boundaries (batch is SORTED) ---------
__global__ void k_pre(const int* __restrict__ ei, const int* __restrict__ batch) {
    int t = blockIdx.x * 256 + threadIdx.x;
    if (t < NE) atomicAdd(&g_deg[ei[NE + t]], 1);
    if (t < NN) {
        int bt = batch[t];
        if (t == 0) {
            for (int g = 0; g <= bt; g++) g_goff[g] = 0;
        } else {
            int bp = batch[t - 1];
            for (int g = bp + 1; g <= bt; g++) g_goff[g] = t;
        }
        if (t == NN - 1) {
            for (int g = bt + 1; g <= NG; g++) g_goff[g] = NN;
        }
    }
}

// ------ scan phase 1: per-block sums of (deg-1) ------------------------------
__global__ void k_scan1() {
    __shared__ int sw[8];
    int t = blockIdx.x * 256 + threadIdx.x;
    int v = (t < NN) ? (g_deg[t] - 1) : 0;
    #pragma unroll
    for (int o = 16; o > 0; o >>= 1) v += __shfl_xor_sync(0xffffffffu, v, o);
    if ((threadIdx.x & 31) == 0) sw[threadIdx.x >> 5] = v;
    __syncthreads();
    if (threadIdx.x == 0) {
        int s = 0;
        #pragma unroll
        for (int w = 0; w < 8; w++) s += sw[w];
        g_bsum[blockIdx.x] = s;
    }
}

// ------ scan phase 2+3: block base via local 196-scan, in-block scan, dinv --
__global__ void k_scan3() {
    __shared__ int sb[256];
    __shared__ int s[256];
    int tid = threadIdx.x;
    int t = blockIdx.x * 256 + tid;
    sb[tid] = (tid < SCAN_B) ? g_bsum[tid] : 0;
    int dg = (t < NN) ? g_deg[t] : 1;
    int v = dg - 1;
    s[tid] = v;
    __syncthreads();
    #pragma unroll
    for (int off = 1; off < 256; off <<= 1) {
        int u  = (tid >= off) ? s[tid - off]  : 0;
        int ub = (tid >= off) ? sb[tid - off] : 0;
        __syncthreads();
        s[tid] += u;
        sb[tid] += ub;
        __syncthreads();
    }
    if (t < NN) {
        int base = blockIdx.x ? sb[blockIdx.x - 1] : 0;
        g_coff[t] = base + s[tid] - v;               // exclusive
        g_dinv[t] = rsqrtf((float)dg);
    }
}

// ---- fused lin0(+relu), @Wc, and dinv pre-scale; 8 nodes per iter -----------
__global__ void k_lin0(const float* __restrict__ x, const float* __restrict__ W0,
                       const float* __restrict__ b0, const float* __restrict__ Wc) {
    __shared__ float sW0[IND * DIM];
    __shared__ float sWc[DIM * DIM];
    __shared__ float sb0[DIM];
    __shared__ float sx[8][IND + 1];
    __shared__ float sh[8][DIM];
    int tid = threadIdx.x;                           // 256 threads
    for (int i = tid; i < IND * DIM; i += 256) sW0[i] = W0[i];
    for (int i = tid; i < DIM * DIM; i += 256) sWc[i] = Wc[i];
    if (tid < DIM) sb0[tid] = b0[tid];
    __syncthreads();
    int d = tid & 63, l0 = tid >> 6;                 // l0 in 0..3
    for (int base = blockIdx.x * 8; base < NN; base += gridDim.x * 8) {
        for (int i = tid; i < 8 * IND; i += 256) {
            int nn = i / IND, kk = i % IND;
            int node = base + nn;
            sx[nn][kk] = (node < NN) ? x[node * IND + kk] : 0.f;
        }
        __syncthreads();
        #pragma unroll
        for (int ln = l0; ln < 8; ln += 4) {
            float acc = sb0[d];
            #pragma unroll
            for (int k = 0; k < IND; k++) acc += sx[ln][k] * sW0[k * DIM + d];
            sh[ln][d] = fmaxf(acc, 0.f);
        }
        __syncthreads();
        #pragma unroll
        for (int ln = l0; ln < 8; ln += 4) {
            float acc2 = 0.f;
            #pragma unroll
            for (int k = 0; k < DIM; k++) acc2 += sh[ln][k] * sWc[k * DIM + d];
            int node = base + ln;
            if (node < NN) g_hw[node * DIM + d] = acc2 * g_dinv[node];
        }
        __syncthreads();
    }
}

// ------ CSR placement: src list grouped by target ---------------------------
__global__ void k_place(const int* __restrict__ ei) {
    int t = blockIdx.x * 256 + threadIdx.x;
    if (t >= NE) return;
    int r = ei[t];
    int c = ei[NE + t];
    int pos = atomicAdd(&g_cur[c], 1);
    g_src[g_coff[c] + pos] = r;
}

// ------ gather (no atomics): h2 = relu(dn*(hw'[n] + sum hw'[src]) + bc) -----
// 16 lanes per node (float4), 2 nodes per warp, 4-way unrolled neighbor loop.
__global__ void k_gather(const float* __restrict__ bc) {
    int warp_id = blockIdx.x * 8 + (threadIdx.x >> 5);
    int lane = threadIdx.x & 31;
    int half = lane >> 4, hl = lane & 15;
    int n = warp_id * 2 + half;
    if (n >= NN) return;
    unsigned hmask = half ? 0xffff0000u : 0x0000ffffu;
    const float4* hw4 = (const float4*)g_hw;
    float dn = g_dinv[n];
    float4 acc = hw4[n * 16 + hl];                   // self term (hw pre-scaled)
    int e0 = g_coff[n], e1 = g_coff[n + 1];
    for (int base = e0; base < e1; base += 16) {
        int m = min(16, e1 - base);
        int s = (hl < m) ? g_src[base + hl] : 0;
        int j = 0;
        for (; j + 4 <= m; j += 4) {
            int s0 = __shfl_sync(hmask, s, j,     16);
            int s1 = __shfl_sync(hmask, s, j + 1, 16);
            int s2 = __shfl_sync(hmask, s, j + 2, 16);
            int s3 = __shfl_sync(hmask, s, j + 3, 16);
            float4 v0 = hw4[s0 * 16 + hl];
            float4 v1 = hw4[s1 * 16 + hl];
            float4 v2 = hw4[s2 * 16 + hl];
            float4 v3 = hw4[s3 * 16 + hl];
            acc.x += (v0.x + v1.x) + (v2.x + v3.x);
            acc.y += (v0.y + v1.y) + (v2.y + v3.y);
            acc.z += (v0.z + v1.z) + (v2.z + v3.z);
            acc.w += (v0.w + v1.w) + (v2.w + v3.w);
        }
        for (; j < m; j++) {
            int sj = __shfl_sync(hmask, s, j, 16);
            float4 v = hw4[sj * 16 + hl];
            acc.x += v.x; acc.y += v.y; acc.z += v.z; acc.w += v.w;
        }
    }
    float4 b = ((const float4*)bc)[hl];
    float4 o;
    o.x = fmaxf(dn * acc.x + b.x, 0.f);
    o.y = fmaxf(dn * acc.y + b.y, 0.f);
    o.z = fmaxf(dn * acc.z + b.z, 0.f);
    o.w = fmaxf(dn * acc.w + b.w, 0.f);
    ((float4*)g_h2)[n * 16 + hl] = o;
}

// ------ fully fused Set2Set: 3 x (gates + LSTM cell + attention) + readout --
// one block per graph, 128 threads (4 warps). All state lives in shared.
// Gate weights are read from the TRANSPOSED packed g_Q: lanes contiguous.
__global__ void k_s2s(const float* __restrict__ bih, const float* __restrict__ bhh,
                      const float* __restrict__ W1, const float* __restrict__ b1,
                      const float* __restrict__ W2, const float* __restrict__ b2,
                      float* __restrict__ out) {
    int g = blockIdx.x;
    int tid = threadIdx.x;
    int warp = tid >> 5, lane = tid & 31;
    __shared__ __align__(16) float s_hr[128];   // [h(64), r(64)]
    __shared__ __align__(16) float s_c[DIM];
    __shared__ float s_gate[256];
    __shared__ float sm[4], ssm[4];
    __shared__ float sr[4][DIM];
    __shared__ float red[DIM];

    int start = g_goff[g], end = g_goff[g + 1];
    float bsum0 = bih[tid] + bhh[tid];
    float bsum1 = bih[tid + 128] + bhh[tid + 128];
    s_hr[tid] = 0.f;
    if (tid < DIM) s_c[tid] = 0.f;
    __syncthreads();

    for (int step = 0; step < STEPS; step++) {
        // ---- gates: outputs tid and tid+128, coalesced weight reads ----
        float acc0 = bsum0, acc1 = bsum1;
        if (step > 0) {
            const float2* hr2 = (const float2*)s_hr;
            #pragma unroll 16
            for (int k2 = 0; k2 < 64; k2++) {
                float4 w = g_Q[k2 * 128 + tid];
                float2 hv = hr2[k2];
                acc0 += w.x * hv.x + w.z * hv.y;
                acc1 += w.y * hv.x + w.w * hv.y;
            }
        }
        s_gate[tid] = acc0;
        s_gate[tid + 128] = acc1;
        __syncthreads();
        // ---- LSTM cell ----
        if (tid < DIM) {
            float i = 1.f / (1.f + __expf(-s_gate[tid]));
            float f = 1.f / (1.f + __expf(-s_gate[64 + tid]));
            float gg = tanhf(s_gate[128 + tid]);
            float o = 1.f / (1.f + __expf(-s_gate[192 + tid]));
            float c = f * s_c[tid] + i * gg;
            s_c[tid] = c;
            s_hr[tid] = o * tanhf(c);               // h part
        }
        __syncthreads();
        // ---- attention: dual-stream online softmax over this graph's nodes --
        float q2x = s_hr[lane * 2], q2y = s_hr[lane * 2 + 1];
        float m0 = -1e30f, ws0 = 0.f, rx0 = 0.f, ry0 = 0.f;
        float m1 = -1e30f, ws1 = 0.f, rx1 = 0.f, ry1 = 0.f;
        for (int v = start + warp; v < end; v += 8) {
            int v2 = v + 4;
            bool has1 = (v2 < end);
            float2 hva = ((const float2*)g_h2)[v * 32 + lane];
            float2 hvb = has1 ? ((const float2*)g_h2)[v2 * 32 + lane]
                              : make_float2(0.f, 0.f);
            float da = hva.x * q2x + hva.y * q2y;
            float db = hvb.x * q2x + hvb.y * q2y;
            #pragma unroll
            for (int o = 16; o > 0; o >>= 1) {
                da += __shfl_xor_sync(0xffffffffu, da, o);
                db += __shfl_xor_sync(0xffffffffu, db, o);
            }
            {
                float nm = fmaxf(m0, da);
                float sc = __expf(m0 - nm);
                float w = __expf(da - nm);
                ws0 = ws0 * sc + w;
                rx0 = rx0 * sc + w * hva.x;
                ry0 = ry0 * sc + w * hva.y;
                m0 = nm;
            }
            if (has1) {
                float nm = fmaxf(m1, db);
                float sc = __expf(m1 - nm);
                float w = __expf(db - nm);
                ws1 = ws1 * sc + w;
                rx1 = rx1 * sc + w * hvb.x;
                ry1 = ry1 * sc + w * hvb.y;
                m1 = nm;
            }
        }
        // merge streams
        float m = fmaxf(m0, m1);
        float e0 = __expf(m0 - m), e1 = __expf(m1 - m);
        float wsum = ws0 * e0 + ws1 * e1;
        float rx = rx0 * e0 + rx1 * e1;
        float ry = ry0 * e0 + ry1 * e1;
        if (lane == 0) { sm[warp] = m; ssm[warp] = wsum; }
        sr[warp][lane * 2] = rx;
        sr[warp][lane * 2 + 1] = ry;
        __syncthreads();
        if (tid < DIM) {
            float M = fmaxf(fmaxf(sm[0], sm[1]), fmaxf(sm[2], sm[3]));
            float tot = 0.f, racc = 0.f;
            #pragma unroll
            for (int w = 0; w < 4; w++) {
                float e = __expf(sm[w] - M);
                tot += ssm[w] * e;
                racc += sr[w][tid] * e;
            }
            s_hr[64 + tid] = (end > start) ? racc / tot : 0.f;   // r part
        }
        __syncthreads();
    }
    // ---- readout: relu([h, r] @ W1 + b1) @ W2 + b2 ----
    if (tid < DIM) {
        float acc = b1[tid];
        #pragma unroll
        for (int k = 0; k < 128; k++) acc += s_hr[k] * W1[k * 64 + tid];
        acc = fmaxf(acc, 0.f) * W2[tid];
        #pragma unroll
        for (int o = 16; o > 0; o >>= 1) acc += __shfl_xor_sync(0xffffffffu, acc, o);
        if (lane == 0) red[warp] = acc;
    }
    __syncthreads();
    if (tid == 0) out[g] = red[0] + red[1] + b2[0];
}

// ---------------- launch sequence -------------------------------------------
extern "C" void kernel_launch(void* const* d_in, const int* in_sizes, int n_in,
                              void* d_out, int out_size) {
    const float* x     = (const float*)d_in[0];
    const int*   ei    = (const int*)  d_in[1];
    const int*   batch = (const int*)  d_in[2];
    const float* W0    = (const float*)d_in[3];
    const float* b0    = (const float*)d_in[4];
    const float* Wc    = (const float*)d_in[5];
    const float* bc    = (const float*)d_in[6];
    const float* Wih   = (const float*)d_in[7];
    const float* Whh   = (const float*)d_in[8];
    const float* bih   = (const float*)d_in[9];
    const float* bhh   = (const float*)d_in[10];
    const float* W1    = (const float*)d_in[11];
    const float* b1    = (const float*)d_in[12];
    const float* W2    = (const float*)d_in[13];
    const float* b2    = (const float*)d_in[14];
    float* out = (float*)d_out;

    k_init<<<SCAN_B, 256>>>(Wih, Whh);
    k_pre<<<(NE + 255) / 256, 256>>>(ei, batch);
    k_scan1<<<SCAN_B, 256>>>();
    k_scan3<<<SCAN_B, 256>>>();
    k_lin0<<<512, 256>>>(x, W0, b0, Wc);
    k_place<<<(NE + 255) / 256, 256>>>(ei);
    k_gather<<<(NN / 2 + 7) / 8, 256>>>(bc);
    k_s2s<<<NG, 128>>>(bih, bhh, W1, b1, W2, b2, out);
}

// round 10
// speedup vs baseline: 2.3048x; 1.1110x over previous
#include <cuda_runtime.h>
#include <math.h>

#define NN 50000
#define NE 800000
#define NG 1024
#define IND 25
#define DIM 64
#define STEPS 3
#define SCAN_B 196                     // ceil(NN/256)

// ---------------- device scratch (statically allocated; no cudaMalloc) ------
__device__ float g_hw[NN * DIM];      // dinv[n] * (relu(x@W0+b0) @ Wc)   (pre-scaled!)
__device__ float g_h2[NN * DIM];      // relu(agg + bc)  -> set2set input
__device__ float g_dinv[NN];
__device__ int   g_deg[NN];           // degree incl. self loop
__device__ int   g_cur[NN];           // placement cursors
__device__ int   g_coff[NN + 1];      // CSR offsets (in-edges, excl. self)
__device__ int   g_src[NE];           // CSR source list
__device__ int   g_goff[NG + 1];      // per-graph node ranges (batch sorted)
__device__ int   g_bsum[SCAN_B];      // per-block partial sums
// Transposed+packed gate weights: Q[k2*128 + j] =
//   { W(j,2k2), W(j+128,2k2), W(j,2k2+1), W(j+128,2k2+1) },
//   W(row,k) = Wih[row][k] + (k<64 ? Whh[row][k] : 0)
__device__ float4 g_Q[64 * 128];

// ------ init: deg=1, cursors, coff[NN], transposed gate weights -------------
__global__ void k_init(const float* __restrict__ Wih, const float* __restrict__ Whh) {
    int t = blockIdx.x * 256 + threadIdx.x;
    if (t < NN) { g_deg[t] = 1; g_cur[t] = 0; }
    if (t < 64 * 128) {
        int j = t & 127, k2 = t >> 7;
        int k0 = 2 * k2, k1 = k0 + 1;
        float4 q;
        q.x = Wih[j * 128 + k0]         + (k0 < 64 ? Whh[j * 64 + k0] : 0.f);
        q.y = Wih[(j + 128) * 128 + k0] + (k0 < 64 ? Whh[(j + 128) * 64 + k0] : 0.f);
        q.z = Wih[j * 128 + k1]         + (k1 < 64 ? Whh[j * 64 + k1] : 0.f);
        q.w = Wih[(j + 128) * 128 + k1] + (k1 < 64 ? Whh[(j + 128) * 64 + k1] : 0.f);
        g_Q[t] = q;
    }
    if (t == 0) g_coff[NN] = NE;      // sum(deg-1) == NE identically
}

// ------ degree histogram + graph-range boundaries (batch is SORTED) ---------
__global__ void k_pre(const int* __restrict__ ei, const int* __restrict__ batch) {
    int t = blockIdx.x * 256 + threadIdx.x;
    if (t < NE) atomicAdd(&g_deg[ei[NE + t]], 1);
    if (t < NN) {
        int bt = batch[t];
        if (t == 0) {
            for (int g = 0; g <= bt; g++) g_goff[g] = 0;
        } else {
            int bp = batch[t - 1];
            for (int g = bp + 1; g <= bt; g++) g_goff[g] = t;
        }
        if (t == NN - 1) {
            for (int g = bt + 1; g <= NG; g++) g_goff[g] = NN;
        }
    }
}

// ------ scan phase 1: per-block sums of (deg-1) ------------------------------
__global__ void k_scan1() {
    __shared__ int sw[8];
    int t = blockIdx.x * 256 + threadIdx.x;
    int v = (t < NN) ? (g_deg[t] - 1) : 0;
    #pragma unroll
    for (int o = 16; o > 0; o >>= 1) v += __shfl_xor_sync(0xffffffffu, v, o);
    if ((threadIdx.x & 31) == 0) sw[threadIdx.x >> 5] = v;
    __syncthreads();
    if (threadIdx.x == 0) {
        int s = 0;
        #pragma unroll
        for (int w = 0; w < 8; w++) s += sw[w];
        g_bsum[blockIdx.x] = s;
    }
}

// ------ scan phase 2+3: block base via local 196-scan, in-block scan, dinv --
__global__ void k_scan3() {
    __shared__ int sb[256];
    __shared__ int s[256];
    int tid = threadIdx.x;
    int t = blockIdx.x * 256 + tid;
    sb[tid] = (tid < SCAN_B) ? g_bsum[tid] : 0;
    int dg = (t < NN) ? g_deg[t] : 1;
    int v = dg - 1;
    s[tid] = v;
    __syncthreads();
    #pragma unroll
    for (int off = 1; off < 256; off <<= 1) {
        int u  = (tid >= off) ? s[tid - off]  : 0;
        int ub = (tid >= off) ? sb[tid - off] : 0;
        __syncthreads();
        s[tid] += u;
        sb[tid] += ub;
        __syncthreads();
    }
    if (t < NN) {
        int base = blockIdx.x ? sb[blockIdx.x - 1] : 0;
        g_coff[t] = base + s[tid] - v;               // exclusive
        g_dinv[t] = rsqrtf((float)dg);
    }
}

// ---- fused lin0(+relu), @Wc, dinv pre-scale; register-blocked, LDS.128 -----
// 16-node tiles (NN = 3125*16 exactly). Thread = (d, node-group of 4).
// Weights transposed in shared so the k-loop is float4 over contiguous rows.
__global__ void k_lin0(const float* __restrict__ x, const float* __restrict__ W0,
                       const float* __restrict__ b0, const float* __restrict__ Wc) {
    __shared__ __align__(16) float sW0T[DIM][28];   // [d][k], zero-pad k>=25
    __shared__ __align__(16) float sWcT[DIM][68];   // [d][k], 4 pad words
    __shared__ float sb0[DIM];
    __shared__ __align__(16) float sx[16][28];      // [node][k], zero-padded
    __shared__ __align__(16) float sh[16][68];      // [node][k]
    __shared__ float sdin[16];
    int tid = threadIdx.x;                           // 256 threads
    for (int i = tid; i < DIM * 28; i += 256) {
        int d = i / 28, k = i % 28;
        sW0T[d][k] = (k < IND) ? W0[k * DIM + d] : 0.f;
    }
    for (int i = tid; i < DIM * DIM; i += 256) {
        int k = i >> 6, d = i & 63;
        sWcT[d][k] = Wc[i];
    }
    if (tid < DIM) sb0[tid] = b0[tid];
    __syncthreads();
    int d = tid & 63, ng = tid >> 6;                 // ng in 0..3 -> 4 nodes
    int n0l = ng * 4;
    for (int base = blockIdx.x * 16; base < NN; base += gridDim.x * 16) {
        for (int i = tid; i < 16 * 28; i += 256) {
            int nn = i / 28, k = i % 28;
            sx[nn][k] = (k < IND) ? x[(base + nn) * IND + k] : 0.f;
        }
        if (tid < 16) sdin[tid] = g_dinv[base + tid];
        __syncthreads();
        // ---- stage 1: h = relu(x@W0 + b0), 4 nodes per thread ----
        {
            float a0 = sb0[d], a1 = a0, a2 = a0, a3 = a0;
            const float4* w4 = (const float4*)sW0T[d];
            const float4* x0 = (const float4*)sx[n0l + 0];
            const float4* x1 = (const float4*)sx[n0l + 1];
            const float4* x2 = (const float4*)sx[n0l + 2];
            const float4* x3 = (const float4*)sx[n0l + 3];
            #pragma unroll
            for (int k4 = 0; k4 < 7; k4++) {
                float4 w = w4[k4];
                float4 v0 = x0[k4], v1 = x1[k4], v2 = x2[k4], v3 = x3[k4];
                a0 += w.x * v0.x + w.y * v0.y + w.z * v0.z + w.w * v0.w;
                a1 += w.x * v1.x + w.y * v1.y + w.z * v1.z + w.w * v1.w;
                a2 += w.x * v2.x + w.y * v2.y + w.z * v2.z + w.w * v2.w;
                a3 += w.x * v3.x + w.y * v3.y + w.z * v3.z + w.w * v3.w;
            }
            sh[n0l + 0][d] = fmaxf(a0, 0.f);
            sh[n0l + 1][d] = fmaxf(a1, 0.f);
            sh[n0l + 2][d] = fmaxf(a2, 0.f);
            sh[n0l + 3][d] = fmaxf(a3, 0.f);
        }
        __syncthreads();
        // ---- stage 2: hw = (h@Wc) * dinv ----
        {
            float c0 = 0.f, c1 = 0.f, c2 = 0.f, c3 = 0.f;
            const float4* u4 = (const float4*)sWcT[d];
            const float4* h0 = (const float4*)sh[n0l + 0];
            const float4* h1 = (const float4*)sh[n0l + 1];
            const float4* h2 = (const float4*)sh[n0l + 2];
            const float4* h3 = (const float4*)sh[n0l + 3];
            #pragma unroll
            for (int k4 = 0; k4 < 16; k4++) {
                float4 w = u4[k4];
                float4 v0 = h0[k4], v1 = h1[k4], v2 = h2[k4], v3 = h3[k4];
                c0 += w.x * v0.x + w.y * v0.y + w.z * v0.z + w.w * v0.w;
                c1 += w.x * v1.x + w.y * v1.y + w.z * v1.z + w.w * v1.w;
                c2 += w.x * v2.x + w.y * v2.y + w.z * v2.z + w.w * v2.w;
                c3 += w.x * v3.x + w.y * v3.y + w.z * v3.z + w.w * v3.w;
            }
            int n0 = base + n0l;
            g_hw[(n0 + 0) * DIM + d] = c0 * sdin[n0l + 0];
            g_hw[(n0 + 1) * DIM + d] = c1 * sdin[n0l + 1];
            g_hw[(n0 + 2) * DIM + d] = c2 * sdin[n0l + 2];
            g_hw[(n0 + 3) * DIM + d] = c3 * sdin[n0l + 3];
        }
        __syncthreads();
    }
}

// ------ CSR placement: src list grouped by target ---------------------------
__global__ void k_place(const int* __restrict__ ei) {
    int t = blockIdx.x * 256 + threadIdx.x;
    if (t >= NE) return;
    int r = ei[t];
    int c = ei[NE + t];
    int pos = atomicAdd(&g_cur[c], 1);
    g_src[g_coff[c] + pos] = r;
}

// ------ gather (no atomics): h2 = relu(dn*(hw'[n] + sum hw'[src]) + bc) -----
// 16 lanes per node (float4), 2 nodes per warp, 4-way unrolled neighbor loop.
__global__ void k_gather(const float* __restrict__ bc) {
    int warp_id = blockIdx.x * 8 + (threadIdx.x >> 5);
    int lane = threadIdx.x & 31;
    int half = lane >> 4, hl = lane & 15;
    int n = warp_id * 2 + half;
    if (n >= NN) return;
    unsigned hmask = half ? 0xffff0000u : 0x0000ffffu;
    const float4* hw4 = (const float4*)g_hw;
    float dn = g_dinv[n];
    float4 acc = hw4[n * 16 + hl];                   // self term (hw pre-scaled)
    int e0 = g_coff[n], e1 = g_coff[n + 1];
    for (int base = e0; base < e1; base += 16) {
        int m = min(16, e1 - base);
        int s = (hl < m) ? g_src[base + hl] : 0;
        int j = 0;
        for (; j + 4 <= m; j += 4) {
            int s0 = __shfl_sync(hmask, s, j,     16);
            int s1 = __shfl_sync(hmask, s, j + 1, 16);
            int s2 = __shfl_sync(hmask, s, j + 2, 16);
            int s3 = __shfl_sync(hmask, s, j + 3, 16);
            float4 v0 = hw4[s0 * 16 + hl];
            float4 v1 = hw4[s1 * 16 + hl];
            float4 v2 = hw4[s2 * 16 + hl];
            float4 v3 = hw4[s3 * 16 + hl];
            acc.x += (v0.x + v1.x) + (v2.x + v3.x);
            acc.y += (v0.y + v1.y) + (v2.y + v3.y);
            acc.z += (v0.z + v1.z) + (v2.z + v3.z);
            acc.w += (v0.w + v1.w) + (v2.w + v3.w);
        }
        for (; j < m; j++) {
            int sj = __shfl_sync(hmask, s, j, 16);
            float4 v = hw4[sj * 16 + hl];
            acc.x += v.x; acc.y += v.y; acc.z += v.z; acc.w += v.w;
        }
    }
    float4 b = ((const float4*)bc)[hl];
    float4 o;
    o.x = fmaxf(dn * acc.x + b.x, 0.f);
    o.y = fmaxf(dn * acc.y + b.y, 0.f);
    o.z = fmaxf(dn * acc.z + b.z, 0.f);
    o.w = fmaxf(dn * acc.w + b.w, 0.f);
    ((float4*)g_h2)[n * 16 + hl] = o;
}

// ------ fully fused Set2Set: 3 x (gates + LSTM cell + attention) + readout --
// one block per graph, 128 threads (4 warps). All state lives in shared.
// Gate weights are read from the TRANSPOSED packed g_Q: lanes contiguous.
__global__ void k_s2s(const float* __restrict__ bih, const float* __restrict__ bhh,
                      const float* __restrict__ W1, const float* __restrict__ b1,
                      const float* __restrict__ W2, const float* __restrict__ b2,
                      float* __restrict__ out) {
    int g = blockIdx.x;
    int tid = threadIdx.x;
    int warp = tid >> 5, lane = tid & 31;
    __shared__ __align__(16) float s_hr[128];   // [h(64), r(64)]
    __shared__ __align__(16) float s_c[DIM];
    __shared__ float s_gate[256];
    __shared__ float sm[4], ssm[4];
    __shared__ float sr[4][DIM];
    __shared__ float red[DIM];

    int start = g_goff[g], end = g_goff[g + 1];
    float bsum0 = bih[tid] + bhh[tid];
    float bsum1 = bih[tid + 128] + bhh[tid + 128];
    s_hr[tid] = 0.f;
    if (tid < DIM) s_c[tid] = 0.f;
    __syncthreads();

    for (int step = 0; step < STEPS; step++) {
        // ---- gates: outputs tid and tid+128, coalesced weight reads ----
        float acc0 = bsum0, acc1 = bsum1;
        if (step > 0) {
            const float2* hr2 = (const float2*)s_hr;
            #pragma unroll 16
            for (int k2 = 0; k2 < 64; k2++) {
                float4 w = g_Q[k2 * 128 + tid];
                float2 hv = hr2[k2];
                acc0 += w.x * hv.x + w.z * hv.y;
                acc1 += w.y * hv.x + w.w * hv.y;
            }
        }
        s_gate[tid] = acc0;
        s_gate[tid + 128] = acc1;
        __syncthreads();
        // ---- LSTM cell ----
        if (tid < DIM) {
            float i = 1.f / (1.f + __expf(-s_gate[tid]));
            float f = 1.f / (1.f + __expf(-s_gate[64 + tid]));
            float gg = tanhf(s_gate[128 + tid]);
            float o = 1.f / (1.f + __expf(-s_gate[192 + tid]));
            float c = f * s_c[tid] + i * gg;
            s_c[tid] = c;
            s_hr[tid] = o * tanhf(c);               // h part
        }
        __syncthreads();
        // ---- attention: dual-stream online softmax over this graph's nodes --
        float q2x = s_hr[lane * 2], q2y = s_hr[lane * 2 + 1];
        float m0 = -1e30f, ws0 = 0.f, rx0 = 0.f, ry0 = 0.f;
        float m1 = -1e30f, ws1 = 0.f, rx1 = 0.f, ry1 = 0.f;
        for (int v = start + warp; v < end; v += 8) {
            int v2 = v + 4;
            bool has1 = (v2 < end);
            float2 hva = ((const float2*)g_h2)[v * 32 + lane];
            float2 hvb = has1 ? ((const float2*)g_h2)[v2 * 32 + lane]
                              : make_float2(0.f, 0.f);
            float da = hva.x * q2x + hva.y * q2y;
            float db = hvb.x * q2x + hvb.y * q2y;
            #pragma unroll
            for (int o = 16; o > 0; o >>= 1) {
                da += __shfl_xor_sync(0xffffffffu, da, o);
                db += __shfl_xor_sync(0xffffffffu, db, o);
            }
            {
                float nm = fmaxf(m0, da);
                float sc = __expf(m0 - nm);
                float w = __expf(da - nm);
                ws0 = ws0 * sc + w;
                rx0 = rx0 * sc + w * hva.x;
                ry0 = ry0 * sc + w * hva.y;
                m0 = nm;
            }
            if (has1) {
                float nm = fmaxf(m1, db);
                float sc = __expf(m1 - nm);
                float w = __expf(db - nm);
                ws1 = ws1 * sc + w;
                rx1 = rx1 * sc + w * hvb.x;
                ry1 = ry1 * sc + w * hvb.y;
                m1 = nm;
            }
        }
        // merge streams
        float m = fmaxf(m0, m1);
        float e0 = __expf(m0 - m), e1 = __expf(m1 - m);
        float wsum = ws0 * e0 + ws1 * e1;
        float rx = rx0 * e0 + rx1 * e1;
        float ry = ry0 * e0 + ry1 * e1;
        if (lane == 0) { sm[warp] = m; ssm[warp] = wsum; }
        sr[warp][lane * 2] = rx;
        sr[warp][lane * 2 + 1] = ry;
        __syncthreads();
        if (tid < DIM) {
            float M = fmaxf(fmaxf(sm[0], sm[1]), fmaxf(sm[2], sm[3]));
            float tot = 0.f, racc = 0.f;
            #pragma unroll
            for (int w = 0; w < 4; w++) {
                float e = __expf(sm[w] - M);
                tot += ssm[w] * e;
                racc += sr[w][tid] * e;
            }
            s_hr[64 + tid] = (end > start) ? racc / tot : 0.f;   // r part
        }
        __syncthreads();
    }
    // ---- readout: relu([h, r] @ W1 + b1) @ W2 + b2 ----
    if (tid < DIM) {
        float acc = b1[tid];
        #pragma unroll
        for (int k = 0; k < 128; k++) acc += s_hr[k] * W1[k * 64 + tid];
        acc = fmaxf(acc, 0.f) * W2[tid];
        #pragma unroll
        for (int o = 16; o > 0; o >>= 1) acc += __shfl_xor_sync(0xffffffffu, acc, o);
        if (lane == 0) red[warp] = acc;
    }
    __syncthreads();
    if (tid == 0) out[g] = red[0] + red[1] + b2[0];
}

// ---------------- launch sequence -------------------------------------------
extern "C" void kernel_launch(void* const* d_in, const int* in_sizes, int n_in,
                              void* d_out, int out_size) {
    const float* x     = (const float*)d_in[0];
    const int*   ei    = (const int*)  d_in[1];
    const int*   batch = (const int*)  d_in[2];
    const float* W0    = (const float*)d_in[3];
    const float* b0    = (const float*)d_in[4];
    const float* Wc    = (const float*)d_in[5];
    const float* bc    = (const float*)d_in[6];
    const float* Wih   = (const float*)d_in[7];
    const float* Whh   = (const float*)d_in[8];
    const float* bih   = (const float*)d_in[9];
    const float* bhh   = (const float*)d_in[10];
    const float* W1    = (const float*)d_in[11];
    const float* b1    = (const float*)d_in[12];
    const float* W2    = (const float*)d_in[13];
    const float* b2    = (const float*)d_in[14];
    float* out = (float*)d_out;

    k_init<<<SCAN_B, 256>>>(Wih, Whh);
    k_pre<<<(NE + 255) / 256, 256>>>(ei, batch);
    k_scan1<<<SCAN_B, 256>>>();
    k_scan3<<<SCAN_B, 256>>>();
    k_lin0<<<512, 256>>>(x, W0, b0, Wc);
    k_place<<<(NE + 255) / 256, 256>>>(ei);
    k_gather<<<(NN / 2 + 7) / 8, 256>>>(bc);
    k_s2s<<<NG, 128>>>(bih, bhh, W1, b1, W2, b2, out);
}